// round 16
// baseline (speedup 1.0000x reference)
#include <cuda_runtime.h>
#include <math.h>

// Problem constants
#define NMAT 16384
#define P 33                 // pitch for the tiny single-warp kernels only
#define NWARPS 4             // warps per block in batched kernels
#define NBLK (NMAT / NWARPS) // 4096 blocks, 1 matrix per warp
#define SWEEPS_BATCH 5
#define SWEEPS_SINGLE 7

// ---------------- device scratch (static globals: allowed) ----------------
__device__ float g_part[64 * 1024];          // bm partial sums / reduced GT partials
__device__ float g_bm_sq[1024];              // bm^{1/2}
__device__ float g_isq[1024];                // bm^{-1/2} (symmetric)
__device__ float g_GT_part[(size_t)NBLK * 1024]; // 16 MB: XT partial sums
__device__ float g_Linv[1024];               // L^{-1} row-major (lower, upper=0)
__device__ float g_LinvT[1024];              // L^{-T} row-major
__device__ float g_Lw[1024];                 // chol(weight) row-major
__device__ float g_LwT[1024];                // Lw^T row-major
__device__ float g_vcT[(size_t)NMAT * 1024]; // 64 MB: eigenvectors of Xc, TRANSPOSED: [k][i]
__device__ float g_logw[NMAT * 32];          // log eigenvalues of Xc
__device__ float g_dist_part[NBLK];          // Frechet variance partials
__device__ float g_factor[1];

// ---------------- register-resident Jacobi (XOR ordering) ----------------
// Thread `lane` holds column `lane` of symmetric A in a[0..31] and ROW `lane`
// of V in v[0..31]. Returns eigenvalue for eigenvector column `lane`.
// csc: per-warp float2[16] shared scratch (16B-aligned) — the 16 lo-lanes
// write (c,s) compacted by pair-index k; row phase reads 8x LDS.128 broadcast.
// Rotation uses the stable-tangent form t = 2apq/(d + sign(d)*hypot(d,2apq)),
// algebraically identical to sign(th)/(|th|+sqrt(th^2+1)), shorter chain.
__device__ __forceinline__ float warp_eig_sym_reg(float a[32], float v[32],
                                                  float2* csc, int lane, int sweeps) {
    const unsigned FULL = 0xffffffffu;
#pragma unroll
    for (int i = 0; i < 32; i++) v[i] = (i == lane) ? 1.f : 0.f;
    float diag = 0.f, apq = 0.f;
    int p1 = lane ^ 1;
#pragma unroll
    for (int k = 0; k < 32; k++) {
        diag = (k == lane) ? a[k] : diag;
        apq  = (k == p1)   ? a[k] : apq;
    }
    const float4* c4 = reinterpret_cast<const float4*>(csc);
    for (int sw = 0; sw < sweeps; sw++) {
#pragma unroll
        for (int m = 1; m < 32; m++) {
            int t0 = m; t0 |= t0 >> 1; t0 |= t0 >> 2; t0 |= t0 >> 4;
            const int lmask = t0 >> 1;
            const int mn = (m == 31) ? 1 : (m + 1);
            bool is_lo = lane < (lane ^ m);
            // --- rotation (both lanes of the pair compute identically) ---
            float apq_s = 0.5f * (apq + __shfl_xor_sync(FULL, apq, m));
            float dp  = __shfl_xor_sync(FULL, diag, m);
            float dd  = is_lo ? (dp - diag) : (diag - dp);   // aqq - app
            float two_apq = 2.f * apq_s;
            float h2  = fmaf(dd, dd, two_apq * two_apq);
            float h   = h2 * rsqrtf(h2);                     // hypot(dd, 2apq)
            float den = dd + copysignf(h, dd);
            float tt  = __fdividef(two_apq, den);
            float t_eff = (fabsf(apq_s) > 1e-12f) ? tt : 0.f;
            float c = rsqrtf(fmaf(t_eff, t_eff, 1.f));
            float s = t_eff * c;
            float s_signed = is_lo ? -s : s;
            float t_signed = is_lo ? -t_eff : t_eff;
            diag = fmaf(t_signed, apq_s, diag);              // analytic diag update
            // compacted coefficient stage: lo lane -> csc[k]
            if (is_lo) {
                int kk = ((lane >> 1) & ~lmask) | (lane & lmask);
                csc[kk] = make_float2(c, s);
            }
            __syncwarp();
            // --- register-local: row mix of A (J^T A) + column mix of V (V J) ---
#pragma unroll
            for (int t = 0; t < 8; t++) {
                float4 f = c4[t];
                {
                    const int k = 2 * t;
                    const int i = ((k & ~lmask) << 1) | (k & lmask);
                    const int j = i ^ m;
                    float ci = f.x, si = f.y;
                    float x = a[i], y = a[j];
                    a[i] = ci * x - si * y;
                    a[j] = si * x + ci * y;
                    float vx = v[i], vy = v[j];
                    v[i] = ci * vx - si * vy;
                    v[j] = si * vx + ci * vy;
                }
                {
                    const int k = 2 * t + 1;
                    const int i = ((k & ~lmask) << 1) | (k & lmask);
                    const int j = i ^ m;
                    float ci = f.z, si = f.w;
                    float x = a[i], y = a[j];
                    a[i] = ci * x - si * y;
                    a[j] = si * x + ci * y;
                    float vx = v[i], vy = v[j];
                    v[i] = ci * vx - si * vy;
                    v[j] = si * vx + ci * vy;
                }
            }
            // --- cross-thread column mix of A (A J) + next-round apq tracking ---
            float napq = apq;
            int pn = lane ^ mn;
#pragma unroll
            for (int k = 0; k < 32; k++) {
                float ax = __shfl_xor_sync(FULL, a[k], m);
                a[k] = fmaf(s_signed, ax, c * a[k]);
                napq = (k == pn) ? a[k] : napq;
            }
            apq = napq;
        }
    }
    return diag;
}

// acc[0..31] = column `lane` of (A @ B) where A is 32x32 row-major pitch-32
// (16B-aligned shared) read via vectorized broadcast, b[k] = B[k][lane] in regs.
__device__ __forceinline__ void gemm_colA(const float* __restrict__ A,
                                          const float b[32], float acc[32]) {
    const float4* A4 = reinterpret_cast<const float4*>(A);
#pragma unroll
    for (int i = 0; i < 32; i++) {
        float s = 0.f;
#pragma unroll
        for (int k4 = 0; k4 < 8; k4++) {
            float4 av = A4[i * 8 + k4];
            s = fmaf(av.x, b[4 * k4 + 0], s);
            s = fmaf(av.y, b[4 * k4 + 1], s);
            s = fmaf(av.z, b[4 * k4 + 2], s);
            s = fmaf(av.w, b[4 * k4 + 3], s);
        }
        acc[i] = s;
    }
}

// ---- old pitch-33 helpers (tiny single-warp kernels only) ----
__device__ __forceinline__ void wmm(const float* A, const float* B, float* C, int lane) {
    __syncwarp();
    float col[32];
#pragma unroll
    for (int i = 0; i < 32; i++) col[i] = 0.f;
#pragma unroll 4
    for (int k = 0; k < 32; k++) {
        float b = B[k * P + lane];
#pragma unroll
        for (int i = 0; i < 32; i++) col[i] = fmaf(A[i * P + k], b, col[i]);
    }
    __syncwarp();
#pragma unroll
    for (int i = 0; i < 32; i++) C[i * P + lane] = col[i];
    __syncwarp();
}

__device__ void warp_chol(float* A, int lane) {
    for (int j = 0; j < 32; j++) {
        if (lane == 0) A[j * P + j] = sqrtf(A[j * P + j]);
        __syncwarp();
        float d = A[j * P + j];
        if (lane > j) A[lane * P + j] /= d;
        __syncwarp();
        float ll = (lane > j) ? A[lane * P + j] : 0.f;
        for (int k = j + 1; k < 32; k++) {
            float lkj = A[k * P + j];
            if (lane >= k) A[lane * P + k] -= ll * lkj;
        }
        __syncwarp();
    }
}

__device__ void warp_trisolve(const float* L, float* Y, int lane) {
    for (int i = 0; i < 32; i++) {
        float rhs = (i == lane) ? 1.f : 0.f;
        for (int k = 0; k < i; k++) rhs -= L[i * P + k] * Y[k * P + lane];
        Y[i * P + lane] = rhs / L[i * P + i];
        __syncwarp();
    }
}

// ---------------- K1: partial sums for bm ----------------
__global__ void __launch_bounds__(1024) k1_bm_partial(const float* __restrict__ X) {
    int tid = threadIdx.x;
    const float* base = X + (size_t)blockIdx.x * 256 * 1024 + tid;
    float s = 0.f;
#pragma unroll 4
    for (int b = 0; b < 256; b++) s += base[(size_t)b * 1024];
    g_part[blockIdx.x * 1024 + tid] = s;
}

// ---------------- K2: bm eigh -> bm^{1/2}, bm^{-1/2} (ONE WARP) ----------------
__global__ void __launch_bounds__(32) k2_bm_sqrt() {
    __shared__ float V[32 * P], g[32];
    __shared__ __align__(16) float2 csc[16];
    int lane = threadIdx.x;
    float a[32], v[32];
#pragma unroll
    for (int i = 0; i < 32; i++) {
        float s = 0.f;
        for (int blk = 0; blk < 64; blk++) s += g_part[blk * 1024 + i * 32 + lane];
        a[i] = s * (1.f / (float)NMAT);
    }
    float diag = warp_eig_sym_reg(a, v, csc, lane, SWEEPS_SINGLE);
#pragma unroll
    for (int k = 0; k < 32; k++) V[lane * P + k] = v[k];
    g[lane] = sqrtf(diag);
    __syncwarp();
    {   // bm_sq = V diag(sw) V^T
        float col[32];
#pragma unroll
        for (int i = 0; i < 32; i++) col[i] = 0.f;
        for (int k = 0; k < 32; k++) {
            float b = g[k] * V[lane * P + k];
#pragma unroll
            for (int i = 0; i < 32; i++) col[i] = fmaf(V[i * P + k], b, col[i]);
        }
#pragma unroll
        for (int i = 0; i < 32; i++) g_bm_sq[i * 32 + lane] = col[i];
    }
    {   // bm_isq = V diag(1/sw) V^T
        float col[32];
#pragma unroll
        for (int i = 0; i < 32; i++) col[i] = 0.f;
        for (int k = 0; k < 32; k++) {
            float b = V[lane * P + k] / g[k];
#pragma unroll
            for (int i = 0; i < 32; i++) col[i] = fmaf(V[i * P + k], b, col[i]);
        }
#pragma unroll
        for (int i = 0; i < 32; i++) g_isq[i * 32 + lane] = col[i];
    }
}

// ---------------- K3: XT = log(isq X isq), partial GT sums ----------------
__global__ void __launch_bounds__(128, 5) k3_logmean(const float* __restrict__ X) {
    __shared__ __align__(16) float shIsq[1024];
    __shared__ __align__(16) float buf[NWARPS][1024];   // X -> S -> VT -> acc
    __shared__ __align__(16) float2 cscs[NWARPS][16];
    __shared__ float shG[NWARPS][32];
    int tid = threadIdx.x, warp = tid >> 5, lane = tid & 31;
    for (int e = tid; e < 1024; e += 128) shIsq[e] = g_isq[e];
    __syncthreads();

    float* bw = buf[warp];
    int b = blockIdx.x * NWARPS + warp;
    const float* Xb = X + (size_t)b * 1024;
#pragma unroll
    for (int i = 0; i < 32; i++) bw[i * 32 + lane] = Xb[i * 32 + lane];
    __syncwarp();

    // S = X @ isq
    float breg[32], acc[32];
#pragma unroll
    for (int k = 0; k < 32; k++) breg[k] = shIsq[k * 32 + lane];
    gemm_colA(bw, breg, acc);
    __syncwarp();
#pragma unroll
    for (int i = 0; i < 32; i++) bw[i * 32 + lane] = acc[i];  // buf = S
    __syncwarp();

    // inner = isq @ S
    float a[32], v[32];
#pragma unroll
    for (int k = 0; k < 32; k++) breg[k] = bw[k * 32 + lane];
    gemm_colA(shIsq, breg, a);
    __syncwarp();

    float diag = warp_eig_sym_reg(a, v, cscs[warp], lane, SWEEPS_BATCH);

    // store V transposed: buf[k][lane] = v[k]
#pragma unroll
    for (int k = 0; k < 32; k++) bw[k * 32 + lane] = v[k];
    shG[warp][lane] = logf(diag);
    __syncwarp();

    // XT column lane: acc[i] = sum_k VT[k][i] * (logw_k * v[k])
    const float4* V4 = reinterpret_cast<const float4*>(bw);
#pragma unroll
    for (int i = 0; i < 32; i++) acc[i] = 0.f;
#pragma unroll
    for (int k = 0; k < 32; k++) {
        float bb = shG[warp][k] * v[k];
#pragma unroll
        for (int i4 = 0; i4 < 8; i4++) {
            float4 vv = V4[k * 8 + i4];
            acc[4 * i4 + 0] = fmaf(vv.x, bb, acc[4 * i4 + 0]);
            acc[4 * i4 + 1] = fmaf(vv.y, bb, acc[4 * i4 + 1]);
            acc[4 * i4 + 2] = fmaf(vv.z, bb, acc[4 * i4 + 2]);
            acc[4 * i4 + 3] = fmaf(vv.w, bb, acc[4 * i4 + 3]);
        }
    }
    // park each warp's XT in its own buffer (VT no longer needed)
#pragma unroll
    for (int i = 0; i < 32; i++) bw[i * 32 + lane] = acc[i];
    __syncthreads();
    // deterministic slice-parallel reduction: warp w sums rows [8w, 8w+8)
#pragma unroll
    for (int r = 0; r < 8; r++) {
        int row = warp * 8 + r;
        float s0 = buf[0][row * 32 + lane];
        float s1 = buf[1][row * 32 + lane];
        float s2 = buf[2][row * 32 + lane];
        float s3 = buf[3][row * 32 + lane];
        g_GT_part[(size_t)blockIdx.x * 1024 + row * 32 + lane] = ((s0 + s1) + s2) + s3;
    }
}

// ---------------- K4a: fold 4096 GT partials -> 64 (into g_part) ----------------
__global__ void __launch_bounds__(1024) k4a_reduce() {
    int tid = threadIdx.x;
    int blk = blockIdx.x;  // 0..63
    float s = 0.f;
#pragma unroll 4
    for (int j = 0; j < 64; j++)
        s += g_GT_part[(size_t)(blk * 64 + j) * 1024 + tid];
    g_part[blk * 1024 + tid] = s;
}

// ---------------- K4: GT -> batch_mean -> Linv/LinvT; Lw/LwT (ONE WARP) ----
__global__ void __launch_bounds__(32) k4_center(const float* __restrict__ weight) {
    __shared__ float A[32 * P], V[32 * P], M[32 * P], S[32 * P], T[32 * P], g[32];
    __shared__ __align__(16) float2 csc[16];
    int lane = threadIdx.x;
    float a[32], v[32];
#pragma unroll
    for (int i = 0; i < 32; i++) {
        float s = 0.f;
        for (int blk = 0; blk < 64; blk++) s += g_part[blk * 1024 + i * 32 + lane];
        a[i] = s * (1.f / (float)NMAT);
    }
    float diag = warp_eig_sym_reg(a, v, csc, lane, SWEEPS_SINGLE);
#pragma unroll
    for (int k = 0; k < 32; k++) V[lane * P + k] = v[k];
    g[lane] = expf(diag);
    __syncwarp();
    {   // M = expm(GT) = V diag(e) V^T
        float col[32];
#pragma unroll
        for (int i = 0; i < 32; i++) col[i] = 0.f;
        for (int k = 0; k < 32; k++) {
            float b = g[k] * V[lane * P + k];
#pragma unroll
            for (int i = 0; i < 32; i++) col[i] = fmaf(V[i * P + k], b, col[i]);
        }
#pragma unroll
        for (int i = 0; i < 32; i++) M[i * P + lane] = col[i];
    }
    __syncwarp();
#pragma unroll
    for (int i = 0; i < 32; i++) S[i * P + lane] = g_bm_sq[i * 32 + lane];
    __syncwarp();
    wmm(S, M, T, lane);  // bm_sq @ expm(GT)
    wmm(T, S, A, lane);  // A = batch_mean
    warp_chol(A, lane);
    warp_trisolve(A, T, lane);  // T = L^{-1}
#pragma unroll
    for (int i = 0; i < 32; i++) {
        float lv = (lane <= i) ? T[i * P + lane] : 0.f;   // Linv[i][lane]
        g_Linv[i * 32 + lane] = lv;
        float lvt = (i <= lane) ? T[lane * P + i] : 0.f;  // LinvT[i][lane]
        g_LinvT[i * 32 + lane] = lvt;
    }
    // Lw = chol(weight)
#pragma unroll
    for (int i = 0; i < 32; i++) M[i * P + lane] = weight[i * 32 + lane];
    __syncwarp();
    warp_chol(M, lane);
#pragma unroll
    for (int i = 0; i < 32; i++) {
        float lv = (lane <= i) ? M[i * P + lane] : 0.f;   // Lw[i][lane]
        g_Lw[i * 32 + lane] = lv;
        float lvt = (i <= lane) ? M[lane * P + i] : 0.f;  // LwT[i][lane]
        g_LwT[i * 32 + lane] = lvt;
    }
}

// ---------------- K5: Xc eig, store vcT/logw, variance partials ----------------
__global__ void __launch_bounds__(128, 5) k5_center_eig(const float* __restrict__ X) {
    __shared__ __align__(16) float shLinv[1024];
    __shared__ __align__(16) float shLinvT[1024];
    __shared__ __align__(16) float buf[NWARPS][1024];   // X -> S
    __shared__ __align__(16) float2 cscs[NWARPS][16];
    __shared__ float shRed[NWARPS];
    int tid = threadIdx.x, warp = tid >> 5, lane = tid & 31;
    for (int e = tid; e < 1024; e += 128) {
        shLinv[e] = g_Linv[e];
        shLinvT[e] = g_LinvT[e];
    }
    __syncthreads();

    float* bw = buf[warp];
    int b = blockIdx.x * NWARPS + warp;
    const float* Xb = X + (size_t)b * 1024;
#pragma unroll
    for (int i = 0; i < 32; i++) bw[i * 32 + lane] = Xb[i * 32 + lane];
    __syncwarp();

    // S = X @ Linv^T
    float breg[32], acc[32];
#pragma unroll
    for (int k = 0; k < 32; k++) breg[k] = shLinvT[k * 32 + lane];
    gemm_colA(bw, breg, acc);
    __syncwarp();
#pragma unroll
    for (int i = 0; i < 32; i++) bw[i * 32 + lane] = acc[i];  // buf = S
    __syncwarp();

    // Xc = Linv @ S
    float a[32], v[32];
#pragma unroll
    for (int k = 0; k < 32; k++) breg[k] = bw[k * 32 + lane];
    gemm_colA(shLinv, breg, a);

    float diag = warp_eig_sym_reg(a, v, cscs[warp], lane, SWEEPS_BATCH);

    // write eigenvectors transposed, coalesced straight from registers
    float* vt = g_vcT + (size_t)b * 1024;
#pragma unroll
    for (int k = 0; k < 32; k++) vt[k * 32 + lane] = v[k];

    float lw = logf(diag);
    g_logw[b * 32 + lane] = lw;

    float d = lw * lw;
#pragma unroll
    for (int off = 16; off; off >>= 1) d += __shfl_xor_sync(0xffffffffu, d, off);
    if (lane == 0) shRed[warp] = d;
    __syncthreads();
    if (tid == 0) {
        float t = 0.f;
        for (int w = 0; w < NWARPS; w++) t += shRed[w];
        g_dist_part[blockIdx.x] = t;
    }
}

// ---------------- K6: scalar factor ----------------
__global__ void __launch_bounds__(256) k6_factor(const float* __restrict__ shift) {
    __shared__ float sh[256];
    int tid = threadIdx.x;
    float s = 0.f;
    for (int i = tid; i < NBLK; i += 256) s += g_dist_part[i];
    sh[tid] = s;
    __syncthreads();
    for (int st = 128; st; st >>= 1) {
        if (tid < st) sh[tid] += sh[tid + st];
        __syncthreads();
    }
    if (tid == 0) {
        float var = sh[0] * (1.f / (float)NMAT);
        g_factor[0] = shift[0] / sqrtf(var + 1e-5f);
    }
}

// ---------------- K7: Xs = vc e^{f logw} vc^T; out = Lw Xs Lw^T ----------------
__global__ void __launch_bounds__(128, 5) k7_output(float* __restrict__ out) {
    __shared__ __align__(16) float shLw[1024];
    __shared__ __align__(16) float shLwT[1024];
    __shared__ __align__(16) float buf[NWARPS][1024];  // VT -> Xs -> W
    __shared__ float shG[NWARPS][32];
    int tid = threadIdx.x, warp = tid >> 5, lane = tid & 31;
    for (int e = tid; e < 1024; e += 128) {
        shLw[e] = g_Lw[e];
        shLwT[e] = g_LwT[e];
    }
    __syncthreads();

    float* bw = buf[warp];
    int b = blockIdx.x * NWARPS + warp;
    float factor = g_factor[0];
    const float* vt = g_vcT + (size_t)b * 1024;
    float v[32];
#pragma unroll
    for (int k = 0; k < 32; k++) {        // coalesced; also yields v[k] = VT[k][lane]
        float val = vt[k * 32 + lane];
        bw[k * 32 + lane] = val;
        v[k] = val;
    }
    shG[warp][lane] = expf(factor * g_logw[b * 32 + lane]);
    __syncwarp();

    // Xs column lane: acc[i] = sum_k VT[k][i] * (e_k * v[k])
    float acc[32];
    const float4* V4 = reinterpret_cast<const float4*>(bw);
#pragma unroll
    for (int i = 0; i < 32; i++) acc[i] = 0.f;
#pragma unroll
    for (int k = 0; k < 32; k++) {
        float bb = shG[warp][k] * v[k];
#pragma unroll
        for (int i4 = 0; i4 < 8; i4++) {
            float4 vv = V4[k * 8 + i4];
            acc[4 * i4 + 0] = fmaf(vv.x, bb, acc[4 * i4 + 0]);
            acc[4 * i4 + 1] = fmaf(vv.y, bb, acc[4 * i4 + 1]);
            acc[4 * i4 + 2] = fmaf(vv.z, bb, acc[4 * i4 + 2]);
            acc[4 * i4 + 3] = fmaf(vv.w, bb, acc[4 * i4 + 3]);
        }
    }
    __syncwarp();
#pragma unroll
    for (int i = 0; i < 32; i++) bw[i * 32 + lane] = acc[i];  // buf = Xs
    __syncwarp();

    // W = Xs @ Lw^T
    float breg[32];
#pragma unroll
    for (int k = 0; k < 32; k++) breg[k] = shLwT[k * 32 + lane];
    gemm_colA(bw, breg, acc);
    __syncwarp();
#pragma unroll
    for (int i = 0; i < 32; i++) bw[i * 32 + lane] = acc[i];  // buf = W
    __syncwarp();

    // out = Lw @ W
#pragma unroll
    for (int k = 0; k < 32; k++) breg[k] = bw[k * 32 + lane];
    gemm_colA(shLw, breg, acc);

    float* ob = out + (size_t)b * 1024;
#pragma unroll
    for (int i = 0; i < 32; i++) ob[i * 32 + lane] = acc[i];
}

// ---------------- launch ----------------
extern "C" void kernel_launch(void* const* d_in, const int* in_sizes, int n_in,
                              void* d_out, int out_size) {
    (void)in_sizes; (void)n_in; (void)out_size;
    const float* X = (const float*)d_in[0];
    const float* weight = (const float*)d_in[1];
    const float* shift = (const float*)d_in[2];
    float* out = (float*)d_out;

    k1_bm_partial<<<64, 1024>>>(X);
    k2_bm_sqrt<<<1, 32>>>();
    k3_logmean<<<NBLK, 128>>>(X);
    k4a_reduce<<<64, 1024>>>();
    k4_center<<<1, 32>>>(weight);
    k5_center_eig<<<NBLK, 128>>>(X);
    k6_factor<<<1, 256>>>(shift);
    k7_output<<<NBLK, 128>>>(out);
}

// round 17
// speedup vs baseline: 1.1609x; 1.1609x over previous
#include <cuda_runtime.h>
#include <math.h>

// Problem constants
#define NMAT 16384
#define P 33                 // pitch for the tiny single-warp kernels only
#define NWARPS 4             // warps per block in batched kernels
#define NBLK (NMAT / NWARPS) // 4096 blocks, 1 matrix per warp
#define SWEEPS_BATCH 5
#define SWEEPS_SINGLE 7

// ---------------- device scratch (static globals: allowed) ----------------
__device__ float g_part[64 * 1024];          // bm partial sums / reduced GT partials
__device__ float g_bm_sq[1024];              // bm^{1/2}
__device__ float g_isq[1024];                // bm^{-1/2} (symmetric)
__device__ float g_GT_part[(size_t)NBLK * 1024]; // 16 MB: XT partial sums
__device__ float g_Linv[1024];               // L^{-1} row-major (lower, upper=0)
__device__ float g_LinvT[1024];              // L^{-T} row-major
__device__ float g_Lw[1024];                 // chol(weight) row-major
__device__ float g_LwT[1024];                // Lw^T row-major
__device__ float g_vcT[(size_t)NMAT * 1024]; // 64 MB: eigenvectors of Xc, TRANSPOSED: [k][i]
__device__ float g_logw[NMAT * 32];          // log eigenvalues of Xc
__device__ float g_dist_part[NBLK];          // Frechet variance partials
__device__ float g_factor[1];

// ---------------- register-resident Jacobi (XOR ordering) ----------------
// Thread `lane` holds column `lane` of symmetric A in a[0..31] and ROW `lane`
// of V in v[0..31]. Returns eigenvalue for eigenvector column `lane`.
// csc: per-warp float2[16] shared scratch (16B-aligned) — the 16 lo-lanes
// write (c,s) compacted by pair-index k; row phase reads 8x LDS.128 broadcast.
// Rotation uses the stable-tangent form t = 2apq/(d + sign(d)*hypot(d,2apq)).
__device__ __forceinline__ float warp_eig_sym_reg(float a[32], float v[32],
                                                  float2* csc, int lane, int sweeps) {
    const unsigned FULL = 0xffffffffu;
#pragma unroll
    for (int i = 0; i < 32; i++) v[i] = (i == lane) ? 1.f : 0.f;
    float diag = 0.f, apq = 0.f;
    int p1 = lane ^ 1;
#pragma unroll
    for (int k = 0; k < 32; k++) {
        diag = (k == lane) ? a[k] : diag;
        apq  = (k == p1)   ? a[k] : apq;
    }
    const float4* c4 = reinterpret_cast<const float4*>(csc);
    for (int sw = 0; sw < sweeps; sw++) {
#pragma unroll
        for (int m = 1; m < 32; m++) {
            int t0 = m; t0 |= t0 >> 1; t0 |= t0 >> 2; t0 |= t0 >> 4;
            const int lmask = t0 >> 1;
            const int mn = (m == 31) ? 1 : (m + 1);
            bool is_lo = lane < (lane ^ m);
            // --- rotation (both lanes of the pair compute identically) ---
            float apq_s = 0.5f * (apq + __shfl_xor_sync(FULL, apq, m));
            float dp  = __shfl_xor_sync(FULL, diag, m);
            float dd  = is_lo ? (dp - diag) : (diag - dp);   // aqq - app
            float two_apq = 2.f * apq_s;
            float h2  = fmaf(dd, dd, two_apq * two_apq);
            float h   = h2 * rsqrtf(h2);                     // hypot(dd, 2apq)
            float den = dd + copysignf(h, dd);
            float tt  = __fdividef(two_apq, den);
            float t_eff = (fabsf(apq_s) > 1e-12f) ? tt : 0.f;
            float c = rsqrtf(fmaf(t_eff, t_eff, 1.f));
            float s = t_eff * c;
            float s_signed = is_lo ? -s : s;
            float t_signed = is_lo ? -t_eff : t_eff;
            diag = fmaf(t_signed, apq_s, diag);              // analytic diag update
            // compacted coefficient stage: lo lane -> csc[k]
            if (is_lo) {
                int kk = ((lane >> 1) & ~lmask) | (lane & lmask);
                csc[kk] = make_float2(c, s);
            }
            __syncwarp();
            // --- register-local: row mix of A (J^T A) + column mix of V (V J) ---
#pragma unroll
            for (int t = 0; t < 8; t++) {
                float4 f = c4[t];
                {
                    const int k = 2 * t;
                    const int i = ((k & ~lmask) << 1) | (k & lmask);
                    const int j = i ^ m;
                    float ci = f.x, si = f.y;
                    float x = a[i], y = a[j];
                    a[i] = ci * x - si * y;
                    a[j] = si * x + ci * y;
                    float vx = v[i], vy = v[j];
                    v[i] = ci * vx - si * vy;
                    v[j] = si * vx + ci * vy;
                }
                {
                    const int k = 2 * t + 1;
                    const int i = ((k & ~lmask) << 1) | (k & lmask);
                    const int j = i ^ m;
                    float ci = f.z, si = f.w;
                    float x = a[i], y = a[j];
                    a[i] = ci * x - si * y;
                    a[j] = si * x + ci * y;
                    float vx = v[i], vy = v[j];
                    v[i] = ci * vx - si * vy;
                    v[j] = si * vx + ci * vy;
                }
            }
            // --- cross-thread column mix of A (A J) + next-round apq tracking ---
            float napq = apq;
            int pn = lane ^ mn;
#pragma unroll
            for (int k = 0; k < 32; k++) {
                float ax = __shfl_xor_sync(FULL, a[k], m);
                a[k] = fmaf(s_signed, ax, c * a[k]);
                napq = (k == pn) ? a[k] : napq;
            }
            apq = napq;
        }
    }
    return diag;
}

// acc[0..31] = column `lane` of (A @ B) where A is 32x32 row-major pitch-32
// (16B-aligned shared) read via vectorized broadcast, b[k] = B[k][lane] in regs.
__device__ __forceinline__ void gemm_colA(const float* __restrict__ A,
                                          const float b[32], float acc[32]) {
    const float4* A4 = reinterpret_cast<const float4*>(A);
#pragma unroll
    for (int i = 0; i < 32; i++) {
        float s = 0.f;
#pragma unroll
        for (int k4 = 0; k4 < 8; k4++) {
            float4 av = A4[i * 8 + k4];
            s = fmaf(av.x, b[4 * k4 + 0], s);
            s = fmaf(av.y, b[4 * k4 + 1], s);
            s = fmaf(av.z, b[4 * k4 + 2], s);
            s = fmaf(av.w, b[4 * k4 + 3], s);
        }
        acc[i] = s;
    }
}

// ---- old pitch-33 helpers (tiny single-warp kernels only) ----
__device__ __forceinline__ void wmm(const float* A, const float* B, float* C, int lane) {
    __syncwarp();
    float col[32];
#pragma unroll
    for (int i = 0; i < 32; i++) col[i] = 0.f;
#pragma unroll 4
    for (int k = 0; k < 32; k++) {
        float b = B[k * P + lane];
#pragma unroll
        for (int i = 0; i < 32; i++) col[i] = fmaf(A[i * P + k], b, col[i]);
    }
    __syncwarp();
#pragma unroll
    for (int i = 0; i < 32; i++) C[i * P + lane] = col[i];
    __syncwarp();
}

__device__ void warp_chol(float* A, int lane) {
    for (int j = 0; j < 32; j++) {
        if (lane == 0) A[j * P + j] = sqrtf(A[j * P + j]);
        __syncwarp();
        float d = A[j * P + j];
        if (lane > j) A[lane * P + j] /= d;
        __syncwarp();
        float ll = (lane > j) ? A[lane * P + j] : 0.f;
        for (int k = j + 1; k < 32; k++) {
            float lkj = A[k * P + j];
            if (lane >= k) A[lane * P + k] -= ll * lkj;
        }
        __syncwarp();
    }
}

__device__ void warp_trisolve(const float* L, float* Y, int lane) {
    for (int i = 0; i < 32; i++) {
        float rhs = (i == lane) ? 1.f : 0.f;
        for (int k = 0; k < i; k++) rhs -= L[i * P + k] * Y[k * P + lane];
        Y[i * P + lane] = rhs / L[i * P + i];
        __syncwarp();
    }
}

// ---------------- K1: partial sums for bm ----------------
__global__ void __launch_bounds__(1024) k1_bm_partial(const float* __restrict__ X) {
    int tid = threadIdx.x;
    const float* base = X + (size_t)blockIdx.x * 256 * 1024 + tid;
    float s = 0.f;
#pragma unroll 4
    for (int b = 0; b < 256; b++) s += base[(size_t)b * 1024];
    g_part[blockIdx.x * 1024 + tid] = s;
}

// ---------------- K2: bm eigh -> bm^{1/2}, bm^{-1/2} (ONE WARP) ----------------
__global__ void __launch_bounds__(32) k2_bm_sqrt() {
    __shared__ float V[32 * P], g[32];
    __shared__ __align__(16) float2 csc[16];
    int lane = threadIdx.x;
    float a[32], v[32];
#pragma unroll
    for (int i = 0; i < 32; i++) {
        float s = 0.f;
        for (int blk = 0; blk < 64; blk++) s += g_part[blk * 1024 + i * 32 + lane];
        a[i] = s * (1.f / (float)NMAT);
    }
    float diag = warp_eig_sym_reg(a, v, csc, lane, SWEEPS_SINGLE);
#pragma unroll
    for (int k = 0; k < 32; k++) V[lane * P + k] = v[k];
    g[lane] = sqrtf(diag);
    __syncwarp();
    {   // bm_sq = V diag(sw) V^T
        float col[32];
#pragma unroll
        for (int i = 0; i < 32; i++) col[i] = 0.f;
        for (int k = 0; k < 32; k++) {
            float b = g[k] * V[lane * P + k];
#pragma unroll
            for (int i = 0; i < 32; i++) col[i] = fmaf(V[i * P + k], b, col[i]);
        }
#pragma unroll
        for (int i = 0; i < 32; i++) g_bm_sq[i * 32 + lane] = col[i];
    }
    {   // bm_isq = V diag(1/sw) V^T
        float col[32];
#pragma unroll
        for (int i = 0; i < 32; i++) col[i] = 0.f;
        for (int k = 0; k < 32; k++) {
            float b = V[lane * P + k] / g[k];
#pragma unroll
            for (int i = 0; i < 32; i++) col[i] = fmaf(V[i * P + k], b, col[i]);
        }
#pragma unroll
        for (int i = 0; i < 32; i++) g_isq[i * 32 + lane] = col[i];
    }
}

// ---------------- K3: XT = log(isq X isq), partial GT sums ----------------
__global__ void __launch_bounds__(128, 4) k3_logmean(const float* __restrict__ X) {
    __shared__ __align__(16) float shIsq[1024];
    __shared__ __align__(16) float buf[NWARPS][1024];   // X -> S -> VT -> acc
    __shared__ __align__(16) float2 cscs[NWARPS][16];
    __shared__ float shG[NWARPS][32];
    int tid = threadIdx.x, warp = tid >> 5, lane = tid & 31;
    for (int e = tid; e < 1024; e += 128) shIsq[e] = g_isq[e];
    __syncthreads();

    float* bw = buf[warp];
    int b = blockIdx.x * NWARPS + warp;
    const float* Xb = X + (size_t)b * 1024;
#pragma unroll
    for (int i = 0; i < 32; i++) bw[i * 32 + lane] = Xb[i * 32 + lane];
    __syncwarp();

    // S = X @ isq
    float breg[32], acc[32];
#pragma unroll
    for (int k = 0; k < 32; k++) breg[k] = shIsq[k * 32 + lane];
    gemm_colA(bw, breg, acc);
    __syncwarp();
#pragma unroll
    for (int i = 0; i < 32; i++) bw[i * 32 + lane] = acc[i];  // buf = S
    __syncwarp();

    // inner = isq @ S
    float a[32], v[32];
#pragma unroll
    for (int k = 0; k < 32; k++) breg[k] = bw[k * 32 + lane];
    gemm_colA(shIsq, breg, a);
    __syncwarp();

    float diag = warp_eig_sym_reg(a, v, cscs[warp], lane, SWEEPS_BATCH);

    // store V transposed: buf[k][lane] = v[k]
#pragma unroll
    for (int k = 0; k < 32; k++) bw[k * 32 + lane] = v[k];
    shG[warp][lane] = logf(diag);
    __syncwarp();

    // XT column lane: acc[i] = sum_k VT[k][i] * (logw_k * v[k])
    const float4* V4 = reinterpret_cast<const float4*>(bw);
#pragma unroll
    for (int i = 0; i < 32; i++) acc[i] = 0.f;
#pragma unroll
    for (int k = 0; k < 32; k++) {
        float bb = shG[warp][k] * v[k];
#pragma unroll
        for (int i4 = 0; i4 < 8; i4++) {
            float4 vv = V4[k * 8 + i4];
            acc[4 * i4 + 0] = fmaf(vv.x, bb, acc[4 * i4 + 0]);
            acc[4 * i4 + 1] = fmaf(vv.y, bb, acc[4 * i4 + 1]);
            acc[4 * i4 + 2] = fmaf(vv.z, bb, acc[4 * i4 + 2]);
            acc[4 * i4 + 3] = fmaf(vv.w, bb, acc[4 * i4 + 3]);
        }
    }
    // park each warp's XT in its own buffer (VT no longer needed)
#pragma unroll
    for (int i = 0; i < 32; i++) bw[i * 32 + lane] = acc[i];
    __syncthreads();
    // deterministic slice-parallel reduction: warp w sums rows [8w, 8w+8)
#pragma unroll
    for (int r = 0; r < 8; r++) {
        int row = warp * 8 + r;
        float s0 = buf[0][row * 32 + lane];
        float s1 = buf[1][row * 32 + lane];
        float s2 = buf[2][row * 32 + lane];
        float s3 = buf[3][row * 32 + lane];
        g_GT_part[(size_t)blockIdx.x * 1024 + row * 32 + lane] = ((s0 + s1) + s2) + s3;
    }
}

// ---------------- K4a: fold 4096 GT partials -> 64 (into g_part) ----------------
__global__ void __launch_bounds__(1024) k4a_reduce() {
    int tid = threadIdx.x;
    int blk = blockIdx.x;  // 0..63
    float s = 0.f;
#pragma unroll 4
    for (int j = 0; j < 64; j++)
        s += g_GT_part[(size_t)(blk * 64 + j) * 1024 + tid];
    g_part[blk * 1024 + tid] = s;
}

// ---------------- K4: GT -> batch_mean -> Linv/LinvT; Lw/LwT (ONE WARP) ----
__global__ void __launch_bounds__(32) k4_center(const float* __restrict__ weight) {
    __shared__ float A[32 * P], V[32 * P], M[32 * P], S[32 * P], T[32 * P], g[32];
    __shared__ __align__(16) float2 csc[16];
    int lane = threadIdx.x;
    float a[32], v[32];
#pragma unroll
    for (int i = 0; i < 32; i++) {
        float s = 0.f;
        for (int blk = 0; blk < 64; blk++) s += g_part[blk * 1024 + i * 32 + lane];
        a[i] = s * (1.f / (float)NMAT);
    }
    float diag = warp_eig_sym_reg(a, v, csc, lane, SWEEPS_SINGLE);
#pragma unroll
    for (int k = 0; k < 32; k++) V[lane * P + k] = v[k];
    g[lane] = expf(diag);
    __syncwarp();
    {   // M = expm(GT) = V diag(e) V^T
        float col[32];
#pragma unroll
        for (int i = 0; i < 32; i++) col[i] = 0.f;
        for (int k = 0; k < 32; k++) {
            float b = g[k] * V[lane * P + k];
#pragma unroll
            for (int i = 0; i < 32; i++) col[i] = fmaf(V[i * P + k], b, col[i]);
        }
#pragma unroll
        for (int i = 0; i < 32; i++) M[i * P + lane] = col[i];
    }
    __syncwarp();
#pragma unroll
    for (int i = 0; i < 32; i++) S[i * P + lane] = g_bm_sq[i * 32 + lane];
    __syncwarp();
    wmm(S, M, T, lane);  // bm_sq @ expm(GT)
    wmm(T, S, A, lane);  // A = batch_mean
    warp_chol(A, lane);
    warp_trisolve(A, T, lane);  // T = L^{-1}
#pragma unroll
    for (int i = 0; i < 32; i++) {
        float lv = (lane <= i) ? T[i * P + lane] : 0.f;   // Linv[i][lane]
        g_Linv[i * 32 + lane] = lv;
        float lvt = (i <= lane) ? T[lane * P + i] : 0.f;  // LinvT[i][lane]
        g_LinvT[i * 32 + lane] = lvt;
    }
    // Lw = chol(weight)
#pragma unroll
    for (int i = 0; i < 32; i++) M[i * P + lane] = weight[i * 32 + lane];
    __syncwarp();
    warp_chol(M, lane);
#pragma unroll
    for (int i = 0; i < 32; i++) {
        float lv = (lane <= i) ? M[i * P + lane] : 0.f;   // Lw[i][lane]
        g_Lw[i * 32 + lane] = lv;
        float lvt = (i <= lane) ? M[lane * P + i] : 0.f;  // LwT[i][lane]
        g_LwT[i * 32 + lane] = lvt;
    }
}

// ---------------- K5: Xc eig, store vcT/logw, variance partials ----------------
__global__ void __launch_bounds__(128, 4) k5_center_eig(const float* __restrict__ X) {
    __shared__ __align__(16) float shLinv[1024];
    __shared__ __align__(16) float shLinvT[1024];
    __shared__ __align__(16) float buf[NWARPS][1024];   // X -> S
    __shared__ __align__(16) float2 cscs[NWARPS][16];
    __shared__ float shRed[NWARPS];
    int tid = threadIdx.x, warp = tid >> 5, lane = tid & 31;
    for (int e = tid; e < 1024; e += 128) {
        shLinv[e] = g_Linv[e];
        shLinvT[e] = g_LinvT[e];
    }
    __syncthreads();

    float* bw = buf[warp];
    int b = blockIdx.x * NWARPS + warp;
    const float* Xb = X + (size_t)b * 1024;
#pragma unroll
    for (int i = 0; i < 32; i++) bw[i * 32 + lane] = Xb[i * 32 + lane];
    __syncwarp();

    // S = X @ Linv^T
    float breg[32], acc[32];
#pragma unroll
    for (int k = 0; k < 32; k++) breg[k] = shLinvT[k * 32 + lane];
    gemm_colA(bw, breg, acc);
    __syncwarp();
#pragma unroll
    for (int i = 0; i < 32; i++) bw[i * 32 + lane] = acc[i];  // buf = S
    __syncwarp();

    // Xc = Linv @ S
    float a[32], v[32];
#pragma unroll
    for (int k = 0; k < 32; k++) breg[k] = bw[k * 32 + lane];
    gemm_colA(shLinv, breg, a);

    float diag = warp_eig_sym_reg(a, v, cscs[warp], lane, SWEEPS_BATCH);

    // write eigenvectors transposed, coalesced straight from registers
    float* vt = g_vcT + (size_t)b * 1024;
#pragma unroll
    for (int k = 0; k < 32; k++) vt[k * 32 + lane] = v[k];

    float lw = logf(diag);
    g_logw[b * 32 + lane] = lw;

    float d = lw * lw;
#pragma unroll
    for (int off = 16; off; off >>= 1) d += __shfl_xor_sync(0xffffffffu, d, off);
    if (lane == 0) shRed[warp] = d;
    __syncthreads();
    if (tid == 0) {
        float t = 0.f;
        for (int w = 0; w < NWARPS; w++) t += shRed[w];
        g_dist_part[blockIdx.x] = t;
    }
}

// ---------------- K6: scalar factor ----------------
__global__ void __launch_bounds__(256) k6_factor(const float* __restrict__ shift) {
    __shared__ float sh[256];
    int tid = threadIdx.x;
    float s = 0.f;
    for (int i = tid; i < NBLK; i += 256) s += g_dist_part[i];
    sh[tid] = s;
    __syncthreads();
    for (int st = 128; st; st >>= 1) {
        if (tid < st) sh[tid] += sh[tid + st];
        __syncthreads();
    }
    if (tid == 0) {
        float var = sh[0] * (1.f / (float)NMAT);
        g_factor[0] = shift[0] / sqrtf(var + 1e-5f);
    }
}

// ---------------- K7: Xs = vc e^{f logw} vc^T; out = Lw Xs Lw^T ----------------
__global__ void __launch_bounds__(128, 4) k7_output(float* __restrict__ out) {
    __shared__ __align__(16) float shLw[1024];
    __shared__ __align__(16) float shLwT[1024];
    __shared__ __align__(16) float buf[NWARPS][1024];  // VT -> Xs -> W
    __shared__ float shG[NWARPS][32];
    int tid = threadIdx.x, warp = tid >> 5, lane = tid & 31;
    for (int e = tid; e < 1024; e += 128) {
        shLw[e] = g_Lw[e];
        shLwT[e] = g_LwT[e];
    }
    __syncthreads();

    float* bw = buf[warp];
    int b = blockIdx.x * NWARPS + warp;
    float factor = g_factor[0];
    const float* vt = g_vcT + (size_t)b * 1024;
    float v[32];
#pragma unroll
    for (int k = 0; k < 32; k++) {        // coalesced; also yields v[k] = VT[k][lane]
        float val = vt[k * 32 + lane];
        bw[k * 32 + lane] = val;
        v[k] = val;
    }
    shG[warp][lane] = expf(factor * g_logw[b * 32 + lane]);
    __syncwarp();

    // Xs column lane: acc[i] = sum_k VT[k][i] * (e_k * v[k])
    float acc[32];
    const float4* V4 = reinterpret_cast<const float4*>(bw);
#pragma unroll
    for (int i = 0; i < 32; i++) acc[i] = 0.f;
#pragma unroll
    for (int k = 0; k < 32; k++) {
        float bb = shG[warp][k] * v[k];
#pragma unroll
        for (int i4 = 0; i4 < 8; i4++) {
            float4 vv = V4[k * 8 + i4];
            acc[4 * i4 + 0] = fmaf(vv.x, bb, acc[4 * i4 + 0]);
            acc[4 * i4 + 1] = fmaf(vv.y, bb, acc[4 * i4 + 1]);
            acc[4 * i4 + 2] = fmaf(vv.z, bb, acc[4 * i4 + 2]);
            acc[4 * i4 + 3] = fmaf(vv.w, bb, acc[4 * i4 + 3]);
        }
    }
    __syncwarp();
#pragma unroll
    for (int i = 0; i < 32; i++) bw[i * 32 + lane] = acc[i];  // buf = Xs
    __syncwarp();

    // W = Xs @ Lw^T
    float breg[32];
#pragma unroll
    for (int k = 0; k < 32; k++) breg[k] = shLwT[k * 32 + lane];
    gemm_colA(bw, breg, acc);
    __syncwarp();
#pragma unroll
    for (int i = 0; i < 32; i++) bw[i * 32 + lane] = acc[i];  // buf = W
    __syncwarp();

    // out = Lw @ W
#pragma unroll
    for (int k = 0; k < 32; k++) breg[k] = bw[k * 32 + lane];
    gemm_colA(shLw, breg, acc);

    float* ob = out + (size_t)b * 1024;
#pragma unroll
    for (int i = 0; i < 32; i++) ob[i * 32 + lane] = acc[i];
}

// ---------------- launch ----------------
extern "C" void kernel_launch(void* const* d_in, const int* in_sizes, int n_in,
                              void* d_out, int out_size) {
    (void)in_sizes; (void)n_in; (void)out_size;
    const float* X = (const float*)d_in[0];
    const float* weight = (const float*)d_in[1];
    const float* shift = (const float*)d_in[2];
    float* out = (float*)d_out;

    k1_bm_partial<<<64, 1024>>>(X);
    k2_bm_sqrt<<<1, 32>>>();
    k3_logmean<<<NBLK, 128>>>(X);
    k4a_reduce<<<64, 1024>>>();
    k4_center<<<1, 32>>>(weight);
    k5_center_eig<<<NBLK, 128>>>(X);
    k6_factor<<<1, 256>>>(shift);
    k7_output<<<NBLK, 128>>>(out);
}